// round 1
// baseline (speedup 1.0000x reference)
#include <cuda_runtime.h>

// Problem constants
#define BB    8
#define CIN   128
#define COUT  128
#define HH    64
#define WW    64
#define HO    64
#define WO    64
#define KK    9        // 3x3
#define HW    (HH*WW)

// Pre-transposed weights: w_t[k][cin][co]
__device__ float g_wt[KK * CIN * COUT];

__global__ void transpose_weight_kernel(const float* __restrict__ weight) {
    int t = blockIdx.x * blockDim.x + threadIdx.x;
    if (t >= KK * CIN * COUT) return;
    int co  = t % COUT;
    int cin = (t / COUT) % CIN;
    int k   = t / (COUT * CIN);
    // weight layout: [co][cin][k]
    g_wt[t] = weight[(co * CIN + cin) * KK + k];
}

__global__ __launch_bounds__(256, 2)
void deform_conv_kernel(const float* __restrict__ x,
                        const float* __restrict__ offset,
                        const float* __restrict__ bias,
                        float* __restrict__ out)
{
    // Sampling data for this output row: 9 taps x 64 pixels, 4 corners each
    __shared__ int   sIdx[4][KK * WO];   // linear index into HxW plane, -1 if OOB
    __shared__ float sWgt[4][KK * WO];   // bilinear weight per corner
    __shared__ float v_s[32][WO];        // sampled values: [cin_local][pix]
    __shared__ float w_s[32][COUT];      // weights: [cin_local][co]

    const int tid = threadIdx.x;
    const int b   = blockIdx.x / HO;
    const int ho  = blockIdx.x % HO;

    // ---- 1. Precompute bilinear sampling (shared across all cin, all cout) ----
    for (int e = tid; e < KK * WO; e += 256) {
        const int k  = e / WO;
        const int wo = e % WO;
        const int kh = k / 3;
        const int kw = k % 3;
        // offset channels: dy at 2k, dx at 2k+1
        const float dy = offset[(((size_t)b * (2 * KK) + 2 * k    ) * HO + ho) * WO + wo];
        const float dx = offset[(((size_t)b * (2 * KK) + 2 * k + 1) * HO + ho) * WO + wo];
        const float py = (float)(ho - 1 + kh) + dy;
        const float px = (float)(wo - 1 + kw) + dx;
        const float y0f = floorf(py);
        const float x0f = floorf(px);
        const float ly = py - y0f;
        const float lx = px - x0f;
        const int y0 = (int)y0f;
        const int x0 = (int)x0f;
        const int y1 = y0 + 1;
        const int x1 = x0 + 1;

        const bool vy0 = (y0 >= 0) && (y0 < HH);
        const bool vy1 = (y1 >= 0) && (y1 < HH);
        const bool vx0 = (x0 >= 0) && (x0 < WW);
        const bool vx1 = (x1 >= 0) && (x1 < WW);

        sIdx[0][e] = (vy0 && vx0) ? (y0 * WW + x0) : -1;
        sIdx[1][e] = (vy0 && vx1) ? (y0 * WW + x1) : -1;
        sIdx[2][e] = (vy1 && vx0) ? (y1 * WW + x0) : -1;
        sIdx[3][e] = (vy1 && vx1) ? (y1 * WW + x1) : -1;
        sWgt[0][e] = (1.0f - ly) * (1.0f - lx);
        sWgt[1][e] = (1.0f - ly) * lx;
        sWgt[2][e] = ly * (1.0f - lx);
        sWgt[3][e] = ly * lx;
    }

    // ---- 2. GEMM: out[co][pix] = sum_{k,cin} w[co][cin][k] * val[cin][k][pix] ----
    const int tx = tid & 15;   // pixel group: 16 groups x 4 px
    const int ty = tid >> 4;   // cout group:  16 groups x 8 co

    float acc[8][4];
    #pragma unroll
    for (int i = 0; i < 8; i++) {
        const float bv = bias[ty * 8 + i];
        #pragma unroll
        for (int j = 0; j < 4; j++) acc[i][j] = bv;
    }

    const float* xb = x + (size_t)b * CIN * HW;

    for (int k = 0; k < KK; k++) {
        for (int c0 = 0; c0 < CIN; c0 += 32) {
            __syncthreads();  // protect v_s/w_s from previous iteration readers

            // gather sampled values for 32 cin x 64 pix
            #pragma unroll
            for (int it = 0; it < 8; it++) {
                const int e   = it * 256 + tid;
                const int pix = e & 63;
                const int ci  = e >> 6;
                const int kb  = k * WO + pix;
                const float* xp = xb + (size_t)(c0 + ci) * HW;
                float v = 0.0f;
                const int i0 = sIdx[0][kb];
                const int i1 = sIdx[1][kb];
                const int i2 = sIdx[2][kb];
                const int i3 = sIdx[3][kb];
                if (i0 >= 0) v = fmaf(sWgt[0][kb], __ldg(xp + i0), v);
                if (i1 >= 0) v = fmaf(sWgt[1][kb], __ldg(xp + i1), v);
                if (i2 >= 0) v = fmaf(sWgt[2][kb], __ldg(xp + i2), v);
                if (i3 >= 0) v = fmaf(sWgt[3][kb], __ldg(xp + i3), v);
                v_s[ci][pix] = v;
            }

            // load weight tile [32 cin][128 co] (coalesced from pre-transposed)
            const float* wt = g_wt + ((size_t)k * CIN + c0) * COUT;
            #pragma unroll
            for (int it = 0; it < 4; it++) {
                const int f = it * 1024 + tid * 4;
                *(float4*)&w_s[f >> 7][f & 127] = *(const float4*)(wt + f);
            }

            __syncthreads();

            // register-blocked FMA: 8 co x 4 pix per thread
            #pragma unroll
            for (int kk = 0; kk < 32; kk++) {
                const float4 v  = *(const float4*)&v_s[kk][tx * 4];
                const float4 wa = *(const float4*)&w_s[kk][ty * 8];
                const float4 wb = *(const float4*)&w_s[kk][ty * 8 + 4];
                const float wv[8] = {wa.x, wa.y, wa.z, wa.w, wb.x, wb.y, wb.z, wb.w};
                const float vv[4] = {v.x, v.y, v.z, v.w};
                #pragma unroll
                for (int i = 0; i < 8; i++)
                    #pragma unroll
                    for (int j = 0; j < 4; j++)
                        acc[i][j] = fmaf(wv[i], vv[j], acc[i][j]);
            }
        }
    }

    // ---- 3. Store ----
    #pragma unroll
    for (int i = 0; i < 8; i++) {
        const int co = ty * 8 + i;
        float4 r = make_float4(acc[i][0], acc[i][1], acc[i][2], acc[i][3]);
        *(float4*)(out + (((size_t)b * COUT + co) * HO + ho) * WO + tx * 4) = r;
    }
}

extern "C" void kernel_launch(void* const* d_in, const int* in_sizes, int n_in,
                              void* d_out, int out_size)
{
    const float* x      = (const float*)d_in[0];
    const float* offset = (const float*)d_in[1];
    const float* weight = (const float*)d_in[2];
    const float* bias   = (const float*)d_in[3];
    float* out = (float*)d_out;

    transpose_weight_kernel<<<(KK * CIN * COUT + 255) / 256, 256>>>(weight);
    deform_conv_kernel<<<BB * HO, 256>>>(x, offset, bias, out);
}

// round 3
// speedup vs baseline: 2.3834x; 2.3834x over previous
#include <cuda_runtime.h>
#include <cstdint>

// ---------------- problem constants ----------------
#define BB    8
#define CINC  128
#define COUT  128
#define HH    64
#define WW    64
#define HW    4096
#define KK    9
#define NCHUNK 36      // K = 1152 = 36 chunks of 32 (chunk c -> tap c>>2, cin block c&3)
#define NPIX  128      // pixels per CTA (2 output rows)
#define VPAD  36       // padded row length (floats) -> conflict-free fragment LDS

// ---------------- dynamic smem layout (bytes) ----------------
#define OFF_IDX  0                    // uchar4[9*128]  = 4608
#define OFF_WGT  4608                 // float4[9*128]  = 18432 -> 23040
#define OFF_V    23040                // float[128*36]  = 18432 -> 41472
#define OFF_W    41472                // float[128*36]  = 18432 -> 59904
#define SMEM_TOTAL 59904

// pre-transposed, tf32-RN-rounded weights: [chunk][co][cin_local(32)]
__device__ float g_wt[NCHUNK * 4096];

__device__ __forceinline__ float to_tf32(float x) {
    float r;
    asm("cvt.rna.tf32.f32 %0, %1;" : "=f"(r) : "f"(x));
    return r;
}

__device__ __forceinline__ void mma_tf32(float* d, const uint32_t* a, uint32_t b0, uint32_t b1) {
    asm volatile(
        "mma.sync.aligned.m16n8k8.row.col.f32.tf32.tf32.f32 "
        "{%0,%1,%2,%3}, {%4,%5,%6,%7}, {%8,%9}, {%0,%1,%2,%3};"
        : "+f"(d[0]), "+f"(d[1]), "+f"(d[2]), "+f"(d[3])
        : "r"(a[0]), "r"(a[1]), "r"(a[2]), "r"(a[3]), "r"(b0), "r"(b1));
}

// ---------------- weight prep (one-time, tiny) ----------------
__global__ void prep_weight_kernel(const float* __restrict__ weight) {
    int t = blockIdx.x * blockDim.x + threadIdx.x;
    if (t >= NCHUNK * 4096) return;
    const int c   = t >> 12;
    const int co  = (t >> 5) & 127;
    const int j   = t & 31;
    const int tap = c >> 2;
    const int cin = ((c & 3) << 5) + j;
    g_wt[t] = to_tf32(weight[(co * CINC + cin) * KK + tap]);
}

// ---------------- main kernel ----------------
__global__ __launch_bounds__(256, 2)
void deform_conv_mma_kernel(const float* __restrict__ x,
                            const float* __restrict__ offs,
                            const float* __restrict__ bias,
                            float* __restrict__ out)
{
    extern __shared__ char smem[];
    uchar4* sIdx = (uchar4*)(smem + OFF_IDX);
    float4* sWgt = (float4*)(smem + OFF_WGT);
    float*  v_s  = (float*)(smem + OFF_V);    // [pix][VPAD], K x N tile (cin x pix)
    float*  w_s  = (float*)(smem + OFF_W);    // [co][VPAD],  M x K tile (co x cin)

    const int tid  = threadIdx.x;
    const int wid  = tid >> 5;
    const int lane = tid & 31;

    const int b   = blockIdx.x >> 5;      // 32 CTAs per image
    const int rp  = blockIdx.x & 31;      // row-pair index
    const int ho0 = rp * 2;

    // ---- 1. sampling tables: 9 taps x 128 pix (clamped corner + per-axis masked weights) ----
    for (int e = tid; e < KK * NPIX; e += 256) {
        const int t  = e >> 7;
        const int pp = e & 127;
        const int ho = ho0 + (pp >> 6);
        const int wo = pp & 63;
        const int kh = t / 3;
        const int kw = t - kh * 3;
        const float* ob = offs + (((size_t)b * (2 * KK) + 2 * t) * HH + ho) * WW + wo;
        const float dy = ob[0];
        const float dx = ob[HW];
        const float py = (float)(ho - 1 + kh) + dy;
        const float px = (float)(wo - 1 + kw) + dx;
        const float y0f = floorf(py), x0f = floorf(px);
        const float ly = py - y0f, lx = px - x0f;
        const int y0 = (int)y0f, x0 = (int)x0f;
        const float wy0 = (y0 >= 0     && y0 < HH)     ? (1.0f - ly) : 0.0f;
        const float wy1 = (y0 + 1 >= 0 && y0 + 1 < HH) ? ly          : 0.0f;
        const float wx0 = (x0 >= 0     && x0 < WW)     ? (1.0f - lx) : 0.0f;
        const float wx1 = (x0 + 1 >= 0 && x0 + 1 < WW) ? lx          : 0.0f;
        const int cy0 = min(max(y0, 0), HH - 1), cy1 = min(max(y0 + 1, 0), HH - 1);
        const int cx0 = min(max(x0, 0), WW - 1), cx1 = min(max(x0 + 1, 0), WW - 1);
        sIdx[e] = make_uchar4((unsigned char)cy0, (unsigned char)cx0,
                              (unsigned char)cy1, (unsigned char)cx1);
        sWgt[e] = make_float4(wy0, wy1, wx0, wx1);
    }
    __syncthreads();

    // ---- 2. GEMM setup ----
    const int pix  = tid & 127;
    const int half = tid >> 7;            // cin block: half*16 .. half*16+15
    const int m0   = (wid & 3) << 5;      // warp cout base (32 wide)
    const int n0   = (wid >> 2) << 6;     // warp pixel base (64 wide)
    const int grp  = lane >> 2;
    const int t4   = lane & 3;

    float acc[2][8][4];
    #pragma unroll
    for (int mt = 0; mt < 2; mt++)
        #pragma unroll
        for (int nt = 0; nt < 8; nt++)
            #pragma unroll
            for (int q = 0; q < 4; q++) acc[mt][nt][q] = 0.0f;

    const float* xB = x + (size_t)b * CINC * HW;

    // ---- 3. chunk loop ----
    for (int c = 0; c < NCHUNK; c++) {
        const int tap  = c >> 2;
        const int cin0 = (c & 3) << 5;

        // bilinear gather: thread = (pix, 16 consecutive cin), STS.128 every 4
        {
            const uchar4 q = sIdx[tap * 128 + pix];
            const float4 w = sWgt[tap * 128 + pix];
            const int i00 = (int)q.x * WW + (int)q.y;
            const int i01 = (int)q.x * WW + (int)q.w;
            const int i10 = (int)q.z * WW + (int)q.y;
            const int i11 = (int)q.z * WW + (int)q.w;
            const float w00 = w.x * w.z, w01 = w.x * w.w;
            const float w10 = w.y * w.z, w11 = w.y * w.w;

            const float* xp = xB + (size_t)(cin0 + half * 16) * HW;
            float* vrow = v_s + pix * VPAD + half * 16;
            #pragma unroll
            for (int jj = 0; jj < 4; jj++) {
                float4 vv;
                float* pv = (float*)&vv;
                #pragma unroll
                for (int e = 0; e < 4; e++) {
                    float v = w00 * __ldg(xp + i00) + w01 * __ldg(xp + i01)
                            + w10 * __ldg(xp + i10) + w11 * __ldg(xp + i11);
                    pv[e] = to_tf32(v);
                    xp += HW;
                }
                *(float4*)(vrow + jj * 4) = vv;
            }
        }

        // weight tile copy: 128 co x 32 cin (16KB) from pre-rounded gmem
        {
            const float4* wsrc = (const float4*)(g_wt + (c << 12));
            #pragma unroll
            for (int it = 0; it < 4; it++) {
                const int i  = it * 256 + tid;        // float4 index in [0,1024)
                const int co = i >> 3;
                const int pt = i & 7;
                *(float4*)(w_s + co * VPAD + pt * 4) = wsrc[i];
            }
        }

        __syncthreads();

        // mma: per warp 32co x 64pix, K=32 in 4 ksteps of 8
        #pragma unroll
        for (int kk = 0; kk < 4; kk++) {
            const int k0 = kk * 8;
            uint32_t a[2][4];
            #pragma unroll
            for (int mt = 0; mt < 2; mt++) {
                const float* wr = w_s + (m0 + mt * 16 + grp) * VPAD + k0 + t4;
                a[mt][0] = __float_as_uint(wr[0]);
                a[mt][1] = __float_as_uint(wr[8 * VPAD]);
                a[mt][2] = __float_as_uint(wr[4]);
                a[mt][3] = __float_as_uint(wr[8 * VPAD + 4]);
            }
            #pragma unroll
            for (int nt = 0; nt < 8; nt++) {
                const float* vr = v_s + (n0 + nt * 8 + grp) * VPAD + k0 + t4;
                const uint32_t b0 = __float_as_uint(vr[0]);
                const uint32_t b1 = __float_as_uint(vr[4]);
                mma_tf32(acc[0][nt], a[0], b0, b1);
                mma_tf32(acc[1][nt], a[1], b0, b1);
            }
        }

        __syncthreads();
    }

    // ---- 4. epilogue: bias + store (float2 per row fragment) ----
    #pragma unroll
    for (int mt = 0; mt < 2; mt++) {
        const int r0 = m0 + mt * 16 + grp;
        const int r1 = r0 + 8;
        const float bv0 = bias[r0];
        const float bv1 = bias[r1];
        float* o0 = out + ((size_t)(b * COUT + r0)) * HW + rp * 128 + n0 + 2 * t4;
        float* o1 = out + ((size_t)(b * COUT + r1)) * HW + rp * 128 + n0 + 2 * t4;
        #pragma unroll
        for (int nt = 0; nt < 8; nt++) {
            *(float2*)(o0 + nt * 8) = make_float2(acc[mt][nt][0] + bv0, acc[mt][nt][1] + bv0);
            *(float2*)(o1 + nt * 8) = make_float2(acc[mt][nt][2] + bv1, acc[mt][nt][3] + bv1);
        }
    }
}

// ---------------- launch ----------------
extern "C" void kernel_launch(void* const* d_in, const int* in_sizes, int n_in,
                              void* d_out, int out_size)
{
    const float* x      = (const float*)d_in[0];
    const float* offset = (const float*)d_in[1];
    const float* weight = (const float*)d_in[2];
    const float* bias   = (const float*)d_in[3];
    float* out = (float*)d_out;

    cudaFuncSetAttribute(deform_conv_mma_kernel,
                         cudaFuncAttributeMaxDynamicSharedMemorySize, SMEM_TOTAL);

    prep_weight_kernel<<<(NCHUNK * 4096 + 255) / 256, 256>>>(weight);
    deform_conv_mma_kernel<<<BB * 32, 256, SMEM_TOTAL>>>(x, offset, bias, out);
}

// round 4
// speedup vs baseline: 3.1370x; 1.3162x over previous
#include <cuda_runtime.h>
#include <cstdint>

// ---------------- problem constants ----------------
#define BB    8
#define CINC  128
#define COUT  128
#define HH    64
#define WW    64
#define HW    4096
#define KK    9
#define NCHUNK 36      // K = 1152 = 36 chunks of 32 (chunk c -> tap c>>2, cin block c&3)
#define NPIX  128      // pixels per CTA (2 output rows)
#define VPAD  36       // padded row length (floats) -> conflict-free fragment LDS

// ---------------- dynamic smem layout (bytes) ----------------
#define OFF_IDX  0                     // ushort4[9*128] = 9216
#define OFF_WGT  9216                  // float4[9*128]  = 18432 -> 27648
#define TILE_BYTES (NPIX * VPAD * 4)   // 18432
#define OFF_V0   27648
#define OFF_V1   (OFF_V0 + TILE_BYTES) // 46080
#define OFF_W0   (OFF_V1 + TILE_BYTES) // 64512
#define OFF_W1   (OFF_W0 + TILE_BYTES) // 82944
#define SMEM_TOTAL (OFF_W1 + TILE_BYTES) // 101376

// pre-transposed, tf32-RN-rounded weights: [chunk][co][cin_local(32)]
__device__ float g_wt[NCHUNK * 4096];
// NHWC-tiled x: xx[b][blk(4)][y][x][cin32]  (16 MB)
__device__ float g_xx[BB * 4 * HW * 32];

__device__ __forceinline__ float to_tf32(float x) {
    float r;
    asm("cvt.rna.tf32.f32 %0, %1;" : "=f"(r) : "f"(x));
    return r;
}

__device__ __forceinline__ void mma_tf32(float* d, const uint32_t* a, uint32_t b0, uint32_t b1) {
    asm volatile(
        "mma.sync.aligned.m16n8k8.row.col.f32.tf32.tf32.f32 "
        "{%0,%1,%2,%3}, {%4,%5,%6,%7}, {%8,%9}, {%0,%1,%2,%3};"
        : "+f"(d[0]), "+f"(d[1]), "+f"(d[2]), "+f"(d[3])
        : "r"(a[0]), "r"(a[1]), "r"(a[2]), "r"(a[3]), "r"(b0), "r"(b1));
}

// ---------------- weight prep (one-time, tiny) ----------------
__global__ void prep_weight_kernel(const float* __restrict__ weight) {
    int t = blockIdx.x * blockDim.x + threadIdx.x;
    if (t >= NCHUNK * 4096) return;
    const int c   = t >> 12;
    const int co  = (t >> 5) & 127;
    const int j   = t & 31;
    const int tap = c >> 2;
    const int cin = ((c & 3) << 5) + j;
    g_wt[t] = to_tf32(weight[(co * CINC + cin) * KK + tap]);
}

// ---------------- x transpose: NCHW -> [b][blk][yx][c32] ----------------
__global__ void transpose_x_kernel(const float* __restrict__ x) {
    __shared__ float ts[32][65];
    const int bid = blockIdx.x;          // 8b * 4blk * 64 yx-tiles = 2048
    const int yxt = bid & 63;
    const int blk = (bid >> 6) & 3;
    const int b   = bid >> 8;
    const int yx0 = yxt * 64;
    const int tid = threadIdx.x;

    // read 32 c x 64 yx (coalesced along yx)
    const int yxl = tid & 63, cl = tid >> 6;
    const float* src = x + (((size_t)(b * CINC + blk * 32)) << 12) + yx0 + yxl;
    #pragma unroll
    for (int i = 0; i < 8; i++) {
        const int c = cl + i * 4;
        ts[c][yxl] = src[(size_t)c << 12];
    }
    __syncthreads();

    // write (coalesced along c)
    float* dst = g_xx + (((size_t)(b * 4 + blk) << 12) + yx0) * 32;
    const int c2 = tid & 31, yq = tid >> 5;
    #pragma unroll
    for (int i = 0; i < 8; i++) {
        const int yx = yq + i * 8;
        dst[(size_t)yx * 32 + c2] = ts[c2][yx];
    }
}

// ---------------- main kernel ----------------
__global__ __launch_bounds__(256, 2)
void deform_conv_mma_kernel(const float* __restrict__ offs,
                            const float* __restrict__ bias,
                            float* __restrict__ out)
{
    extern __shared__ char smem[];
    ushort4* sIdx = (ushort4*)(smem + OFF_IDX);
    float4*  sWgt = (float4*)(smem + OFF_WGT);

    const int tid  = threadIdx.x;
    const int wid  = tid >> 5;
    const int lane = tid & 31;

    const int b   = blockIdx.x >> 5;      // 32 CTAs per image
    const int rp  = blockIdx.x & 31;      // row-pair index
    const int ho0 = rp * 2;

    // ---- 1. sampling tables: 9 taps x 128 pix ----
    for (int e = tid; e < KK * NPIX; e += 256) {
        const int t  = e >> 7;
        const int pp = e & 127;
        const int ho = ho0 + (pp >> 6);
        const int wo = pp & 63;
        const int kh = t / 3;
        const int kw = t - kh * 3;
        const float* ob = offs + (((size_t)b * (2 * KK) + 2 * t) * HH + ho) * WW + wo;
        const float dy = ob[0];
        const float dx = ob[HW];
        const float py = (float)(ho - 1 + kh) + dy;
        const float px = (float)(wo - 1 + kw) + dx;
        const float y0f = floorf(py), x0f = floorf(px);
        const float ly = py - y0f, lx = px - x0f;
        const int y0 = (int)y0f, x0 = (int)x0f;
        const float wy0 = (y0 >= 0     && y0 < HH)     ? (1.0f - ly) : 0.0f;
        const float wy1 = (y0 + 1 >= 0 && y0 + 1 < HH) ? ly          : 0.0f;
        const float wx0 = (x0 >= 0     && x0 < WW)     ? (1.0f - lx) : 0.0f;
        const float wx1 = (x0 + 1 >= 0 && x0 + 1 < WW) ? lx          : 0.0f;
        const int cy0 = min(max(y0, 0), HH - 1), cy1 = min(max(y0 + 1, 0), HH - 1);
        const int cx0 = min(max(x0, 0), WW - 1), cx1 = min(max(x0 + 1, 0), WW - 1);
        sIdx[e] = make_ushort4((unsigned short)(cy0 * WW + cx0),
                               (unsigned short)(cy0 * WW + cx1),
                               (unsigned short)(cy1 * WW + cx0),
                               (unsigned short)(cy1 * WW + cx1));
        sWgt[e] = make_float4(wy0 * wx0, wy0 * wx1, wy1 * wx0, wy1 * wx1);
    }
    __syncthreads();

    // ---- 2. GEMM setup ----
    const int pixg  = tid >> 3;           // pixel group 0..31
    const int lane8 = tid & 7;            // cin quad within chunk
    const int m0    = (wid & 3) << 5;     // warp cout base (32 wide)
    const int n0    = (wid >> 2) << 6;    // warp pixel base (64 wide)
    const int grp   = lane >> 2;
    const int t4    = lane & 3;

    float acc[2][8][4];
    #pragma unroll
    for (int mt = 0; mt < 2; mt++)
        #pragma unroll
        for (int nt = 0; nt < 8; nt++)
            #pragma unroll
            for (int q = 0; q < 4; q++) acc[mt][nt][q] = 0.0f;

    // ---- 3. chunk loop: double-buffered, ONE sync per chunk ----
    for (int c = 0; c < NCHUNK; c++) {
        const int buf = c & 1;
        const int tap = c >> 2;
        const int blk = c & 3;
        float* vb = (float*)(smem + OFF_V0 + buf * TILE_BYTES);
        float* wb = (float*)(smem + OFF_W0 + buf * TILE_BYTES);

        // bilinear gather in NHWC: 8 lanes per pixel, LDG.128 per corner
        {
            const float* pl = g_xx + ((size_t)(b * 4 + blk) << 17);
            #pragma unroll
            for (int pass = 0; pass < 4; pass++) {
                const int pix = pass * 32 + pixg;
                const int e   = tap * 128 + pix;
                const ushort4 q = sIdx[e];
                const float4  w = sWgt[e];
                const float4 a0 = __ldg((const float4*)(pl + (int)q.x * 32) + lane8);
                const float4 a1 = __ldg((const float4*)(pl + (int)q.y * 32) + lane8);
                const float4 a2 = __ldg((const float4*)(pl + (int)q.z * 32) + lane8);
                const float4 a3 = __ldg((const float4*)(pl + (int)q.w * 32) + lane8);
                float4 r;
                r.x = to_tf32(w.x * a0.x + w.y * a1.x + w.z * a2.x + w.w * a3.x);
                r.y = to_tf32(w.x * a0.y + w.y * a1.y + w.z * a2.y + w.w * a3.y);
                r.z = to_tf32(w.x * a0.z + w.y * a1.z + w.z * a2.z + w.w * a3.z);
                r.w = to_tf32(w.x * a0.w + w.y * a1.w + w.z * a2.w + w.w * a3.w);
                *(float4*)(vb + pix * VPAD + lane8 * 4) = r;
            }
        }

        // weight tile copy: 128 co x 32 cin (16KB)
        {
            const float4* wsrc = (const float4*)(g_wt + (c << 12));
            #pragma unroll
            for (int it = 0; it < 4; it++) {
                const int i  = it * 256 + tid;
                const int co = i >> 3;
                const int pt = i & 7;
                *(float4*)(wb + co * VPAD + pt * 4) = wsrc[i];
            }
        }

        __syncthreads();

        // mma: per warp 32co x 64pix, K=32 in 4 ksteps of 8
        #pragma unroll
        for (int kk = 0; kk < 4; kk++) {
            const int k0 = kk * 8;
            uint32_t a[2][4];
            #pragma unroll
            for (int mt = 0; mt < 2; mt++) {
                const float* wr = wb + (m0 + mt * 16 + grp) * VPAD + k0 + t4;
                a[mt][0] = __float_as_uint(wr[0]);
                a[mt][1] = __float_as_uint(wr[8 * VPAD]);
                a[mt][2] = __float_as_uint(wr[4]);
                a[mt][3] = __float_as_uint(wr[8 * VPAD + 4]);
            }
            #pragma unroll
            for (int nt = 0; nt < 8; nt++) {
                const float* vr = vb + (n0 + nt * 8 + grp) * VPAD + k0 + t4;
                const uint32_t b0 = __float_as_uint(vr[0]);
                const uint32_t b1 = __float_as_uint(vr[4]);
                mma_tf32(acc[0][nt], a[0], b0, b1);
                mma_tf32(acc[1][nt], a[1], b0, b1);
            }
        }
        // no trailing sync: next chunk writes the other buffer; the sync above
        // already ordered everyone past mma(c-1) before buf^1 is overwritten.
    }

    // ---- 4. epilogue: bias + store ----
    #pragma unroll
    for (int mt = 0; mt < 2; mt++) {
        const int r0 = m0 + mt * 16 + grp;
        const int r1 = r0 + 8;
        const float bv0 = bias[r0];
        const float bv1 = bias[r1];
        float* o0 = out + ((size_t)(b * COUT + r0)) * HW + rp * 128 + n0 + 2 * t4;
        float* o1 = out + ((size_t)(b * COUT + r1)) * HW + rp * 128 + n0 + 2 * t4;
        #pragma unroll
        for (int nt = 0; nt < 8; nt++) {
            *(float2*)(o0 + nt * 8) = make_float2(acc[mt][nt][0] + bv0, acc[mt][nt][1] + bv0);
            *(float2*)(o1 + nt * 8) = make_float2(acc[mt][nt][2] + bv1, acc[mt][nt][3] + bv1);
        }
    }
}

// ---------------- launch ----------------
extern "C" void kernel_launch(void* const* d_in, const int* in_sizes, int n_in,
                              void* d_out, int out_size)
{
    const float* x      = (const float*)d_in[0];
    const float* offset = (const float*)d_in[1];
    const float* weight = (const float*)d_in[2];
    const float* bias   = (const float*)d_in[3];
    float* out = (float*)d_out;

    cudaFuncSetAttribute(deform_conv_mma_kernel,
                         cudaFuncAttributeMaxDynamicSharedMemorySize, SMEM_TOTAL);

    prep_weight_kernel<<<(NCHUNK * 4096 + 255) / 256, 256>>>(weight);
    transpose_x_kernel<<<2048, 256>>>(x);
    deform_conv_mma_kernel<<<BB * 32, 256, SMEM_TOTAL>>>(offset, bias, out);
}

// round 5
// speedup vs baseline: 3.4474x; 1.0989x over previous
#include <cuda_runtime.h>
#include <cuda_fp16.h>
#include <cstdint>

// ---------------- problem constants ----------------
#define BB    8
#define CINC  128
#define COUT  128
#define HH    64
#define WW    64
#define HW    4096
#define KK    9
#define NCHUNK 36      // K = 1152 = 36 chunks of 32 (chunk c -> tap c>>2, cin block c&3)
#define NPIX  128      // pixels per CTA (2 output rows)
#define VPAD  36       // padded row length (floats) -> conflict-free fragment LDS

// ---------------- dynamic smem layout (bytes) ----------------
#define OFF_IDX  0                     // ushort4[9*128] = 9216
#define OFF_WGT  9216                  // float4[9*128]  = 18432 -> 27648
#define TILE_BYTES (NPIX * VPAD * 4)   // 18432
#define OFF_V0   27648
#define OFF_V1   (OFF_V0 + TILE_BYTES) // 46080
#define SMEM_TOTAL (OFF_V1 + TILE_BYTES) // 64512

// weights pre-permuted into m16n8k8 A-fragment order:
// g_wf[((chunk*4 + kstep)*8 + mblock)*32 + lane] = {a0,a1,a2,a3}
__device__ float4 g_wf[NCHUNK * 4 * 8 * 32];
// NHWC-tiled x in fp16: g_xh[b][blk(4)][yx][cin32]  (8 MB)
__device__ __half g_xh[BB * 4 * HW * 32];

__device__ __forceinline__ float to_tf32(float x) {
    float r;
    asm("cvt.rna.tf32.f32 %0, %1;" : "=f"(r) : "f"(x));
    return r;
}

__device__ __forceinline__ void mma_tf32(float* d, const uint32_t* a, uint32_t b0, uint32_t b1) {
    asm volatile(
        "mma.sync.aligned.m16n8k8.row.col.f32.tf32.tf32.f32 "
        "{%0,%1,%2,%3}, {%4,%5,%6,%7}, {%8,%9}, {%0,%1,%2,%3};"
        : "+f"(d[0]), "+f"(d[1]), "+f"(d[2]), "+f"(d[3])
        : "r"(a[0]), "r"(a[1]), "r"(a[2]), "r"(a[3]), "r"(b0), "r"(b1));
}

// ---------------- weight prep: tf32 round + A-fragment permutation ----------------
__global__ void prep_weight_kernel(const float* __restrict__ weight) {
    const int t = blockIdx.x * blockDim.x + threadIdx.x;
    if (t >= NCHUNK * 4 * 8 * 32) return;
    const int lane = t & 31;
    const int mb   = (t >> 5) & 7;
    const int kk   = (t >> 8) & 3;
    const int c    = t >> 10;
    const int grp = lane >> 2, t4 = lane & 3;
    const int tap = c >> 2;
    const int cin = ((c & 3) << 5) + kk * 8 + t4;
    const int co0 = mb * 16 + grp;
    const int co1 = co0 + 8;
    float4 f;
    f.x = to_tf32(weight[(co0 * CINC + cin    ) * KK + tap]);
    f.y = to_tf32(weight[(co1 * CINC + cin    ) * KK + tap]);
    f.z = to_tf32(weight[(co0 * CINC + cin + 4) * KK + tap]);
    f.w = to_tf32(weight[(co1 * CINC + cin + 4) * KK + tap]);
    g_wf[t] = f;
}

// ---------------- x transpose: NCHW f32 -> [b][blk][yx][c32] fp16 ----------------
__global__ void transpose_x_kernel(const float* __restrict__ x) {
    __shared__ float ts[32][65];
    const int bid = blockIdx.x;          // 8b * 4blk * 64 yx-tiles = 2048
    const int yxt = bid & 63;
    const int blk = (bid >> 6) & 3;
    const int b   = bid >> 8;
    const int yx0 = yxt * 64;
    const int tid = threadIdx.x;

    const int yxl = tid & 63, cl = tid >> 6;
    const float* src = x + (((size_t)(b * CINC + blk * 32)) << 12) + yx0 + yxl;
    #pragma unroll
    for (int i = 0; i < 8; i++) {
        const int c = cl + i * 4;
        ts[c][yxl] = src[(size_t)c << 12];
    }
    __syncthreads();

    __half* dst = g_xh + ((((size_t)(b * 4 + blk)) << 12) + yx0) * 32;
    const int c2 = tid & 31, yq = tid >> 5;
    #pragma unroll
    for (int i = 0; i < 8; i++) {
        const int yx = yq + i * 8;
        dst[(size_t)yx * 32 + c2] = __float2half(ts[c2][yx]);
    }
}

// ---------------- main kernel ----------------
__global__ __launch_bounds__(256, 2)
void deform_conv_mma_kernel(const float* __restrict__ offs,
                            const float* __restrict__ bias,
                            float* __restrict__ out)
{
    extern __shared__ char smem[];
    ushort4* sIdx = (ushort4*)(smem + OFF_IDX);
    float4*  sWgt = (float4*)(smem + OFF_WGT);

    const int tid  = threadIdx.x;
    const int wid  = tid >> 5;
    const int lane = tid & 31;

    const int b   = blockIdx.x >> 5;      // 32 CTAs per image
    const int rp  = blockIdx.x & 31;      // row-pair index
    const int ho0 = rp * 2;

    // ---- 1. sampling tables: 9 taps x 128 pix ----
    for (int e = tid; e < KK * NPIX; e += 256) {
        const int t  = e >> 7;
        const int pp = e & 127;
        const int ho = ho0 + (pp >> 6);
        const int wo = pp & 63;
        const int kh = t / 3;
        const int kw = t - kh * 3;
        const float* ob = offs + (((size_t)b * (2 * KK) + 2 * t) * HH + ho) * WW + wo;
        const float dy = ob[0];
        const float dx = ob[HW];
        const float py = (float)(ho - 1 + kh) + dy;
        const float px = (float)(wo - 1 + kw) + dx;
        const float y0f = floorf(py), x0f = floorf(px);
        const float ly = py - y0f, lx = px - x0f;
        const int y0 = (int)y0f, x0 = (int)x0f;
        const float wy0 = (y0 >= 0     && y0 < HH)     ? (1.0f - ly) : 0.0f;
        const float wy1 = (y0 + 1 >= 0 && y0 + 1 < HH) ? ly          : 0.0f;
        const float wx0 = (x0 >= 0     && x0 < WW)     ? (1.0f - lx) : 0.0f;
        const float wx1 = (x0 + 1 >= 0 && x0 + 1 < WW) ? lx          : 0.0f;
        const int cy0 = min(max(y0, 0), HH - 1), cy1 = min(max(y0 + 1, 0), HH - 1);
        const int cx0 = min(max(x0, 0), WW - 1), cx1 = min(max(x0 + 1, 0), WW - 1);
        sIdx[e] = make_ushort4((unsigned short)(cy0 * WW + cx0),
                               (unsigned short)(cy0 * WW + cx1),
                               (unsigned short)(cy1 * WW + cx0),
                               (unsigned short)(cy1 * WW + cx1));
        sWgt[e] = make_float4(wy0 * wx0, wy0 * wx1, wy1 * wx0, wy1 * wx1);
    }
    __syncthreads();

    // ---- 2. GEMM setup ----
    const int pixg  = tid >> 3;           // pixel group 0..31
    const int lane8 = tid & 7;            // cin quad within chunk (4 cin)
    const int m0    = (wid & 3) << 5;     // warp cout base (32 wide)
    const int mb0   = (wid & 3) << 1;     // warp m-block base (16-row blocks)
    const int n0    = (wid >> 2) << 6;    // warp pixel base (64 wide)
    const int grp   = lane >> 2;
    const int t4    = lane & 3;

    float acc[2][8][4];
    #pragma unroll
    for (int mt = 0; mt < 2; mt++)
        #pragma unroll
        for (int nt = 0; nt < 8; nt++)
            #pragma unroll
            for (int q = 0; q < 4; q++) acc[mt][nt][q] = 0.0f;

    // ---- 3. chunk loop: double-buffered v, ONE sync per chunk ----
    for (int c = 0; c < NCHUNK; c++) {
        const int buf = c & 1;
        const int tap = c >> 2;
        const int blk = c & 3;
        float* vb = (float*)(smem + OFF_V0 + buf * TILE_BYTES);

        // bilinear gather from fp16 NHWC: 8 lanes per pixel, LDG.64 per corner
        {
            const __half* pl = g_xh + ((size_t)(b * 4 + blk) << 17);
            #pragma unroll
            for (int pass = 0; pass < 4; pass++) {
                const int pix = pass * 32 + pixg;
                const int e   = tap * 128 + pix;
                const ushort4 q = sIdx[e];
                const float4  w = sWgt[e];
                const uint2 u0 = __ldg((const uint2*)(pl + (int)q.x * 32) + lane8);
                const uint2 u1 = __ldg((const uint2*)(pl + (int)q.y * 32) + lane8);
                const uint2 u2 = __ldg((const uint2*)(pl + (int)q.z * 32) + lane8);
                const uint2 u3 = __ldg((const uint2*)(pl + (int)q.w * 32) + lane8);
                const float2 a0 = __half22float2(*(const __half2*)&u0.x);
                const float2 b0 = __half22float2(*(const __half2*)&u0.y);
                const float2 a1 = __half22float2(*(const __half2*)&u1.x);
                const float2 b1 = __half22float2(*(const __half2*)&u1.y);
                const float2 a2 = __half22float2(*(const __half2*)&u2.x);
                const float2 b2 = __half22float2(*(const __half2*)&u2.y);
                const float2 a3 = __half22float2(*(const __half2*)&u3.x);
                const float2 b3 = __half22float2(*(const __half2*)&u3.y);
                float4 r;
                r.x = to_tf32(w.x * a0.x + w.y * a1.x + w.z * a2.x + w.w * a3.x);
                r.y = to_tf32(w.x * a0.y + w.y * a1.y + w.z * a2.y + w.w * a3.y);
                r.z = to_tf32(w.x * b0.x + w.y * b1.x + w.z * b2.x + w.w * b3.x);
                r.w = to_tf32(w.x * b0.y + w.y * b1.y + w.z * b2.y + w.w * b3.y);
                *(float4*)(vb + pix * VPAD + lane8 * 4) = r;
            }
        }

        __syncthreads();

        // mma: per warp 32co x 64pix; A-fragments LDG'd directly (pre-permuted, cached)
        #pragma unroll
        for (int kk = 0; kk < 4; kk++) {
            const int k0 = kk * 8;
            const float4 A0 = __ldg(&g_wf[(((c << 2) + kk) * 8 + mb0    ) * 32 + lane]);
            const float4 A1 = __ldg(&g_wf[(((c << 2) + kk) * 8 + mb0 + 1) * 32 + lane]);
            uint32_t a0[4] = {__float_as_uint(A0.x), __float_as_uint(A0.y),
                              __float_as_uint(A0.z), __float_as_uint(A0.w)};
            uint32_t a1[4] = {__float_as_uint(A1.x), __float_as_uint(A1.y),
                              __float_as_uint(A1.z), __float_as_uint(A1.w)};
            #pragma unroll
            for (int nt = 0; nt < 8; nt++) {
                const float* vr = vb + (n0 + nt * 8 + grp) * VPAD + k0 + t4;
                const uint32_t bf0 = __float_as_uint(vr[0]);
                const uint32_t bf1 = __float_as_uint(vr[4]);
                mma_tf32(acc[0][nt], a0, bf0, bf1);
                mma_tf32(acc[1][nt], a1, bf0, bf1);
            }
        }
        // no trailing sync: per-warp program order (mma(c) -> gather(c+1) -> sync)
        // guarantees buf is not rewritten until everyone passed mma(c).
    }

    // ---- 4. epilogue: bias + store ----
    #pragma unroll
    for (int mt = 0; mt < 2; mt++) {
        const int r0 = m0 + mt * 16 + grp;
        const int r1 = r0 + 8;
        const float bv0 = bias[r0];
        const float bv1 = bias[r1];
        float* o0 = out + ((size_t)(b * COUT + r0)) * HW + rp * 128 + n0 + 2 * t4;
        float* o1 = out + ((size_t)(b * COUT + r1)) * HW + rp * 128 + n0 + 2 * t4;
        #pragma unroll
        for (int nt = 0; nt < 8; nt++) {
            *(float2*)(o0 + nt * 8) = make_float2(acc[mt][nt][0] + bv0, acc[mt][nt][1] + bv0);
            *(float2*)(o1 + nt * 8) = make_float2(acc[mt][nt][2] + bv1, acc[mt][nt][3] + bv1);
        }
    }
}

// ---------------- launch ----------------
extern "C" void kernel_launch(void* const* d_in, const int* in_sizes, int n_in,
                              void* d_out, int out_size)
{
    const float* x      = (const float*)d_in[0];
    const float* offset = (const float*)d_in[1];
    const float* weight = (const float*)d_in[2];
    const float* bias   = (const float*)d_in[3];
    float* out = (float*)d_out;

    cudaFuncSetAttribute(deform_conv_mma_kernel,
                         cudaFuncAttributeMaxDynamicSharedMemorySize, SMEM_TOTAL);

    prep_weight_kernel<<<(NCHUNK * 4 * 8 * 32 + 255) / 256, 256>>>(weight);
    transpose_x_kernel<<<2048, 256>>>(x);
    deform_conv_mma_kernel<<<BB * 32, 256, SMEM_TOTAL>>>(offset, bias, out);
}